// round 13
// baseline (speedup 1.0000x reference)
#include <cuda_runtime.h>
#include <cuda_fp16.h>
#include <mma.h>
#include <stdint.h>

using namespace nvcuda;

static constexpr int NN = 100000;
static constexpr int NE = 1600000;
static constexpr int SCAN_BLKS = (NN + 255) / 256;   // 391

// Scratch (device globals — no allocations allowed)
__device__ float  g_dinv[NN];
__device__ __half g_x16[(size_t)NN * 128];
__device__ __half g_p16[(size_t)NN * 128];
__device__ __half g_h16[(size_t)NN * 128];
__device__ __half g_w1h[128 * 128];
__device__ __half g_w2h[128 * 128];
__device__ __half g_w3h[128 * 64];
__device__ int    g_cnt[NN];
__device__ int    g_bsum[SCAN_BLKS];
__device__ int    g_boff[SCAN_BLKS];
__device__ int    g_rowptr[NN + 1];
__device__ int    g_cursor[NN];
__device__ int    g_col[NE];

// ---------------------------------------------------------------------------
// CSR build: histogram -> 3-phase coalesced scan -> scatter
// ---------------------------------------------------------------------------
__global__ void zero_cnt_kernel(int* __restrict__ cnt) {
    int i = blockIdx.x * blockDim.x + threadIdx.x;
    if (i < NN) cnt[i] = 0;
}

__global__ void hist_kernel(const int* __restrict__ ei, int* __restrict__ cnt) {
    int e = blockIdx.x * blockDim.x + threadIdx.x;
    if (e < NE) atomicAdd(&cnt[ei[NE + e]], 1);
}

__global__ __launch_bounds__(256) void scan1_kernel(
    const int* __restrict__ cnt, int* __restrict__ bsum)
{
    __shared__ int warpsum[8];
    int idx = blockIdx.x * 256 + threadIdx.x;
    int c = (idx < NN) ? cnt[idx] : 0;
    int s = c;
    #pragma unroll
    for (int o = 16; o > 0; o >>= 1) s += __shfl_down_sync(0xFFFFFFFFu, s, o);
    if ((threadIdx.x & 31) == 0) warpsum[threadIdx.x >> 5] = s;
    __syncthreads();
    if (threadIdx.x < 8) {
        int t = warpsum[threadIdx.x];
        #pragma unroll
        for (int o = 4; o > 0; o >>= 1) t += __shfl_down_sync(0xFFu, t, o);
        if (threadIdx.x == 0) bsum[blockIdx.x] = t;
    }
}

__global__ __launch_bounds__(512) void scan2_kernel(
    const int* __restrict__ bsum, int* __restrict__ boff,
    int* __restrict__ rowptr)
{
    __shared__ int sh[512];
    int t = threadIdx.x;
    int v = (t < SCAN_BLKS) ? bsum[t] : 0;
    sh[t] = v;
    __syncthreads();
    #pragma unroll
    for (int o = 1; o < 512; o <<= 1) {
        int add = (t >= o) ? sh[t - o] : 0;
        __syncthreads();
        sh[t] += add;
        __syncthreads();
    }
    if (t < SCAN_BLKS) boff[t] = sh[t] - v;
    if (t == SCAN_BLKS - 1) rowptr[NN] = sh[t];
}

__global__ __launch_bounds__(256) void scan3_kernel(
    const int* __restrict__ cnt, const int* __restrict__ boff,
    int* __restrict__ rowptr, int* __restrict__ cursor,
    float* __restrict__ dinv)
{
    __shared__ int warpincl[8];
    int idx = blockIdx.x * 256 + threadIdx.x;
    int lane = threadIdx.x & 31;
    int wid = threadIdx.x >> 5;
    int c = (idx < NN) ? cnt[idx] : 0;

    int incl = c;
    #pragma unroll
    for (int o = 1; o < 32; o <<= 1) {
        int u = __shfl_up_sync(0xFFFFFFFFu, incl, o);
        if (lane >= o) incl += u;
    }
    if (lane == 31) warpincl[wid] = incl;
    __syncthreads();
    if (threadIdx.x < 8) {
        int u = warpincl[threadIdx.x];
        #pragma unroll
        for (int o = 1; o < 8; o <<= 1) {
            int w = __shfl_up_sync(0xFFu, u, o);
            if (threadIdx.x >= o) u += w;
        }
        warpincl[threadIdx.x] = u;
    }
    __syncthreads();
    int base = boff[blockIdx.x] + (wid > 0 ? warpincl[wid - 1] : 0);
    int excl = base + incl - c;
    if (idx < NN) {
        rowptr[idx] = excl;
        cursor[idx] = excl;
        dinv[idx] = rsqrtf((float)(c + 1));
    }
}

__global__ void build_kernel(const int* __restrict__ ei,
                             int* __restrict__ cursor, int* __restrict__ col) {
    int e = blockIdx.x * blockDim.x + threadIdx.x;
    if (e < NE) {
        int s = ei[e];
        int d = ei[NE + e];
        col[atomicAdd(&cursor[d], 1)] = s;
    }
}

// ---------------------------------------------------------------------------
// Prep: fp32 -> fp16 conversions; post-join P row scaling
// ---------------------------------------------------------------------------
__global__ void tohalf_kernel(const float* __restrict__ src,
                              __half* __restrict__ dst, int n4) {
    int i = blockIdx.x * blockDim.x + threadIdx.x;
    if (i < n4) {
        float4 v = ((const float4*)src)[i];
        __half2 h0 = __floats2half2_rn(v.x, v.y);
        __half2 h1 = __floats2half2_rn(v.z, v.w);
        uint2 pack;
        pack.x = *(uint32_t*)&h0;
        pack.y = *(uint32_t*)&h1;
        ((uint2*)dst)[i] = pack;
    }
}

__global__ void pscale_kernel(__half* __restrict__ p,
                              const float* __restrict__ dinv) {
    int i = blockIdx.x * blockDim.x + threadIdx.x;
    if (i < NN * 16) {
        float dv = __ldg(&dinv[i >> 4]);
        uint4 u = ((const uint4*)p)[i];
        __half2* h = (__half2*)&u;
        #pragma unroll
        for (int k = 0; k < 4; k++) {
            float2 f = __half22float2(h[k]);
            h[k] = __floats2half2_rn(f.x * dv, f.y * dv);
        }
        ((uint4*)p)[i] = u;
    }
}

// ---------------------------------------------------------------------------
// wmma fp16 GEMM (m16n16k16, fp32 accum):  P16 = half(A @ W)
// ---------------------------------------------------------------------------
template <int COUT>
__global__ __launch_bounds__(256) void gemm_wmma_kernel(
    const __half* __restrict__ A, const __half* __restrict__ W,
    __half* __restrict__ P)
{
    constexpr int CG = COUT / 64;
    constexpr int CTA_ROWS = (8 / CG) * 32;

    __shared__ float stage[8][16 * 20];

    const int wid = threadIdx.x >> 5;
    const int lane = threadIdx.x & 31;
    const int cg = wid & (CG - 1);
    const int rg = wid / CG;
    const int m0 = blockIdx.x * CTA_ROWS + rg * 32;
    const int n0 = cg * 64;
    if (m0 + 32 > NN) return;

    wmma::fragment<wmma::accumulator, 16, 16, 16, float> acc[2][4];
    #pragma unroll
    for (int i = 0; i < 2; i++)
        #pragma unroll
        for (int j = 0; j < 4; j++) wmma::fill_fragment(acc[i][j], 0.0f);

    #pragma unroll
    for (int k = 0; k < 128; k += 16) {
        wmma::fragment<wmma::matrix_a, 16, 16, 16, __half, wmma::row_major> a[2];
        #pragma unroll
        for (int i = 0; i < 2; i++)
            wmma::load_matrix_sync(a[i], A + (size_t)(m0 + i * 16) * 128 + k, 128);
        #pragma unroll
        for (int j = 0; j < 4; j++) {
            wmma::fragment<wmma::matrix_b, 16, 16, 16, __half, wmma::row_major> b;
            wmma::load_matrix_sync(b, W + (size_t)k * COUT + n0 + j * 16, COUT);
            #pragma unroll
            for (int i = 0; i < 2; i++)
                wmma::mma_sync(acc[i][j], a[i], b, acc[i][j]);
        }
    }

    const int r = lane >> 1;
    const int c0 = (lane & 1) * 8;
    #pragma unroll
    for (int i = 0; i < 2; i++) {
        #pragma unroll
        for (int j = 0; j < 4; j++) {
            wmma::store_matrix_sync(&stage[wid][0], acc[i][j], 20,
                                    wmma::mem_row_major);
            __syncwarp();
            const float* s = &stage[wid][r * 20 + c0];
            __half2 h0 = __floats2half2_rn(s[0], s[1]);
            __half2 h1 = __floats2half2_rn(s[2], s[3]);
            __half2 h2 = __floats2half2_rn(s[4], s[5]);
            __half2 h3 = __floats2half2_rn(s[6], s[7]);
            uint4 pack;
            pack.x = *(uint32_t*)&h0;
            pack.y = *(uint32_t*)&h1;
            pack.z = *(uint32_t*)&h2;
            pack.w = *(uint32_t*)&h3;
            *(uint4*)(P + (size_t)(m0 + i * 16 + r) * COUT + n0 + j * 16 + c0) = pack;
            __syncwarp();
        }
    }
}

// ---------------------------------------------------------------------------
// Gather + finalize: one warp per node, 16-wide main loop with col prefetch.
// ---------------------------------------------------------------------------
__device__ __forceinline__ void add_h4(float4& acc, uint2 u) {
    __half2 a = *(__half2*)&u.x;
    __half2 b = *(__half2*)&u.y;
    float2 fa = __half22float2(a);
    float2 fb = __half22float2(b);
    acc.x += fa.x; acc.y += fa.y; acc.z += fb.x; acc.w += fb.y;
}

template <int COUT, bool RELU, bool SCALE_OUT, bool HALF_OUT>
__global__ __launch_bounds__(256) void gather_kernel(
    const __half* __restrict__ P, const int* __restrict__ rowptr,
    const int* __restrict__ col, const float* __restrict__ dinv,
    const float* __restrict__ bias, void* __restrict__ OUT)
{
    const int v = (int)((blockIdx.x * 256u + threadIdx.x) >> 5);
    const int lane = threadIdx.x & 31;
    if (v >= NN) return;

    const int start = __ldg(&rowptr[v]);
    const int end   = __ldg(&rowptr[v + 1]);
    const float dvv = __ldg(&dinv[v]);

    if (COUT == 128) {
        const size_t off = (size_t)lane * 4;
        float4 acc = make_float4(0.f, 0.f, 0.f, 0.f);
        add_h4(acc, *(const uint2*)(P + (size_t)v * 128 + off));
        int i = start;
        if (i + 15 < end) {
            // software pipeline: prefetch indices one 16-batch ahead
            int s[16];
            #pragma unroll
            for (int u = 0; u < 16; u++) s[u] = __ldg(&col[i + u]);
            for (; i + 31 < end; i += 16) {
                int sn[16];
                #pragma unroll
                for (int u = 0; u < 16; u++) sn[u] = __ldg(&col[i + 16 + u]);
                uint2 t[16];
                #pragma unroll
                for (int u = 0; u < 16; u++)
                    t[u] = *(const uint2*)(P + (size_t)s[u] * 128 + off);
                #pragma unroll
                for (int u = 0; u < 16; u++) add_h4(acc, t[u]);
                #pragma unroll
                for (int u = 0; u < 16; u++) s[u] = sn[u];
            }
            // drain the prefetched batch
            uint2 t[16];
            #pragma unroll
            for (int u = 0; u < 16; u++)
                t[u] = *(const uint2*)(P + (size_t)s[u] * 128 + off);
            #pragma unroll
            for (int u = 0; u < 16; u++) add_h4(acc, t[u]);
            i += 16;
        }
        for (; i + 7 < end; i += 8) {
            int s[8];
            #pragma unroll
            for (int u = 0; u < 8; u++) s[u] = __ldg(&col[i + u]);
            uint2 t[8];
            #pragma unroll
            for (int u = 0; u < 8; u++)
                t[u] = *(const uint2*)(P + (size_t)s[u] * 128 + off);
            #pragma unroll
            for (int u = 0; u < 8; u++) add_h4(acc, t[u]);
        }
        for (; i < end; i++) {
            int s0 = __ldg(&col[i]);
            add_h4(acc, *(const uint2*)(P + (size_t)s0 * 128 + off));
        }
        float4 bb = *(const float4*)(bias + off);
        float4 r = make_float4(fmaf(dvv, acc.x, bb.x), fmaf(dvv, acc.y, bb.y),
                               fmaf(dvv, acc.z, bb.z), fmaf(dvv, acc.w, bb.w));
        if (RELU) {
            r.x = fmaxf(r.x, 0.0f); r.y = fmaxf(r.y, 0.0f);
            r.z = fmaxf(r.z, 0.0f); r.w = fmaxf(r.w, 0.0f);
        }
        if (SCALE_OUT) { r.x *= dvv; r.y *= dvv; r.z *= dvv; r.w *= dvv; }
        if (HALF_OUT) {
            __half2 h0 = __floats2half2_rn(r.x, r.y);
            __half2 h1 = __floats2half2_rn(r.z, r.w);
            uint2 pack;
            pack.x = *(uint32_t*)&h0;
            pack.y = *(uint32_t*)&h1;
            *(uint2*)((__half*)OUT + (size_t)v * 128 + off) = pack;
        } else {
            *(float4*)((float*)OUT + (size_t)v * 128 + off) = r;
        }
    } else {
        const size_t off = (size_t)lane * 2;
        float2 acc = make_float2(0.f, 0.f);
        {
            float2 f = __half22float2(*(const __half2*)(P + (size_t)v * 64 + off));
            acc.x += f.x; acc.y += f.y;
        }
        int i = start;
        for (; i + 15 < end; i += 16) {
            int s[16];
            #pragma unroll
            for (int u = 0; u < 16; u++) s[u] = __ldg(&col[i + u]);
            __half2 t[16];
            #pragma unroll
            for (int u = 0; u < 16; u++)
                t[u] = *(const __half2*)(P + (size_t)s[u] * 64 + off);
            #pragma unroll
            for (int u = 0; u < 16; u++) {
                float2 f = __half22float2(t[u]);
                acc.x += f.x; acc.y += f.y;
            }
        }
        for (; i + 7 < end; i += 8) {
            int s[8];
            #pragma unroll
            for (int u = 0; u < 8; u++) s[u] = __ldg(&col[i + u]);
            __half2 t[8];
            #pragma unroll
            for (int u = 0; u < 8; u++)
                t[u] = *(const __half2*)(P + (size_t)s[u] * 64 + off);
            #pragma unroll
            for (int u = 0; u < 8; u++) {
                float2 f = __half22float2(t[u]);
                acc.x += f.x; acc.y += f.y;
            }
        }
        for (; i < end; i++) {
            int s0 = __ldg(&col[i]);
            float2 f = __half22float2(*(const __half2*)(P + (size_t)s0 * 64 + off));
            acc.x += f.x; acc.y += f.y;
        }
        float2 bb = *(const float2*)(bias + off);
        float2 r = make_float2(fmaf(dvv, acc.x, bb.x), fmaf(dvv, acc.y, bb.y));
        if (RELU) { r.x = fmaxf(r.x, 0.0f); r.y = fmaxf(r.y, 0.0f); }
        if (SCALE_OUT) { r.x *= dvv; r.y *= dvv; }
        if (HALF_OUT) {
            __half2 h = __floats2half2_rn(r.x, r.y);
            *(__half2*)((__half*)OUT + (size_t)v * 64 + off) = h;
        } else {
            *(float2*)((float*)OUT + (size_t)v * 64 + off) = r;
        }
    }
}

// ---------------------------------------------------------------------------
// Launch — fork/join: CSR chain on default stream, prep + GEMM1 on side stream
// ---------------------------------------------------------------------------
extern "C" void kernel_launch(void* const* d_in, const int* in_sizes, int n_in,
                              void* d_out, int out_size) {
    const float* x  = (const float*)d_in[0];
    const int*   ei = (const int*)d_in[1];
    const float* W1 = (const float*)d_in[2];
    const float* b1 = (const float*)d_in[3];
    const float* W2 = (const float*)d_in[4];
    const float* b2 = (const float*)d_in[5];
    const float* W3 = (const float*)d_in[6];
    const float* b3 = (const float*)d_in[7];
    float* out = (float*)d_out;

    float *dinv;
    __half *x16, *p16, *h16, *w1h, *w2h, *w3h;
    int *cnt, *bsum, *boff, *rowptr, *cursor, *col;
    cudaGetSymbolAddress((void**)&dinv,   g_dinv);
    cudaGetSymbolAddress((void**)&x16,    g_x16);
    cudaGetSymbolAddress((void**)&p16,    g_p16);
    cudaGetSymbolAddress((void**)&h16,    g_h16);
    cudaGetSymbolAddress((void**)&w1h,    g_w1h);
    cudaGetSymbolAddress((void**)&w2h,    g_w2h);
    cudaGetSymbolAddress((void**)&w3h,    g_w3h);
    cudaGetSymbolAddress((void**)&cnt,    g_cnt);
    cudaGetSymbolAddress((void**)&bsum,   g_bsum);
    cudaGetSymbolAddress((void**)&boff,   g_boff);
    cudaGetSymbolAddress((void**)&rowptr, g_rowptr);
    cudaGetSymbolAddress((void**)&cursor, g_cursor);
    cudaGetSymbolAddress((void**)&col,    g_col);

    const int TB = 256;
    const int nBlkN      = (NN + TB - 1) / TB;
    const int nBlkE      = (NE + TB - 1) / TB;
    const int gemmBlk128 = (NN + 127) / 128;
    const int gemmBlk64  = (NN + 255) / 256;
    const int gatherBlk  = (NN * 32 + TB - 1) / TB;

    cudaStream_t s2;
    cudaEvent_t eFork, eJoin;
    cudaStreamCreateWithFlags(&s2, cudaStreamNonBlocking);
    cudaEventCreateWithFlags(&eFork, cudaEventDisableTiming);
    cudaEventCreateWithFlags(&eJoin, cudaEventDisableTiming);

    cudaEventRecord(eFork, 0);
    cudaStreamWaitEvent(s2, eFork, 0);

    // side stream: fp16 prep + raw layer-1 GEMM (independent of edge_index)
    tohalf_kernel<<<(128 * 128 / 4 + TB - 1) / TB, TB, 0, s2>>>(W1, w1h, 128 * 128 / 4);
    tohalf_kernel<<<(128 * 128 / 4 + TB - 1) / TB, TB, 0, s2>>>(W2, w2h, 128 * 128 / 4);
    tohalf_kernel<<<(128 * 64 / 4 + TB - 1) / TB, TB, 0, s2>>>(W3, w3h, 128 * 64 / 4);
    tohalf_kernel<<<(NN * 32 + TB - 1) / TB, TB, 0, s2>>>(x, x16, NN * 32);
    gemm_wmma_kernel<128><<<gemmBlk128, TB, 0, s2>>>(x16, w1h, p16);
    cudaEventRecord(eJoin, s2);

    // default stream: CSR build + normalization
    zero_cnt_kernel<<<nBlkN, TB>>>(cnt);
    hist_kernel<<<nBlkE, TB>>>(ei, cnt);
    scan1_kernel<<<SCAN_BLKS, TB>>>(cnt, bsum);
    scan2_kernel<<<1, 512>>>(bsum, boff, rowptr);
    scan3_kernel<<<SCAN_BLKS, TB>>>(cnt, boff, rowptr, cursor, dinv);
    build_kernel<<<nBlkE, TB>>>(ei, cursor, col);

    // join
    cudaStreamWaitEvent(0, eJoin, 0);

    // layer 1: scale P by dinv[row], then gather (emit fp16 h)
    pscale_kernel<<<(NN * 16 + TB - 1) / TB, TB>>>(p16, dinv);
    gather_kernel<128, true, true, true><<<gatherBlk, TB>>>(
        p16, rowptr, col, dinv, b1, h16);
    // layer 2
    gemm_wmma_kernel<128><<<gemmBlk128, TB>>>(h16, w2h, p16);
    gather_kernel<128, true, true, true><<<gatherBlk, TB>>>(
        p16, rowptr, col, dinv, b2, h16);
    // layer 3
    gemm_wmma_kernel<64><<<gemmBlk64, TB>>>(h16, w3h, p16);
    gather_kernel<64, false, false, false><<<gatherBlk, TB>>>(
        p16, rowptr, col, dinv, b3, out);
}

// round 14
// speedup vs baseline: 1.0538x; 1.0538x over previous
#include <cuda_runtime.h>
#include <cuda_fp16.h>
#include <mma.h>
#include <stdint.h>

using namespace nvcuda;

static constexpr int NN = 100000;
static constexpr int NE = 1600000;
static constexpr int SCAN_BLKS = (NN + 255) / 256;   // 391

// Scratch (device globals — no allocations allowed)
__device__ float  g_dinv[NN];
__device__ __half g_x16[(size_t)NN * 128];
__device__ __half g_p16[(size_t)NN * 128];
__device__ __half g_h16[(size_t)NN * 128];
__device__ __half g_w1h[128 * 128];
__device__ __half g_w2h[128 * 128];
__device__ __half g_w3h[128 * 64];
__device__ int    g_cnt[NN];
__device__ int    g_bsum[SCAN_BLKS];
__device__ int    g_boff[SCAN_BLKS];
__device__ int    g_rowptr[NN + 1];
__device__ int    g_cursor[NN];
__device__ int    g_col[NE];

// ---------------------------------------------------------------------------
// CSR build: histogram -> 3-phase coalesced scan -> scatter
// ---------------------------------------------------------------------------
__global__ void zero_cnt_kernel(int* __restrict__ cnt) {
    int i = blockIdx.x * blockDim.x + threadIdx.x;
    if (i < NN) cnt[i] = 0;
}

__global__ void hist_kernel(const int* __restrict__ ei, int* __restrict__ cnt) {
    int e = blockIdx.x * blockDim.x + threadIdx.x;
    if (e < NE) atomicAdd(&cnt[ei[NE + e]], 1);
}

__global__ __launch_bounds__(256) void scan1_kernel(
    const int* __restrict__ cnt, int* __restrict__ bsum)
{
    __shared__ int warpsum[8];
    int idx = blockIdx.x * 256 + threadIdx.x;
    int c = (idx < NN) ? cnt[idx] : 0;
    int s = c;
    #pragma unroll
    for (int o = 16; o > 0; o >>= 1) s += __shfl_down_sync(0xFFFFFFFFu, s, o);
    if ((threadIdx.x & 31) == 0) warpsum[threadIdx.x >> 5] = s;
    __syncthreads();
    if (threadIdx.x < 8) {
        int t = warpsum[threadIdx.x];
        #pragma unroll
        for (int o = 4; o > 0; o >>= 1) t += __shfl_down_sync(0xFFu, t, o);
        if (threadIdx.x == 0) bsum[blockIdx.x] = t;
    }
}

__global__ __launch_bounds__(512) void scan2_kernel(
    const int* __restrict__ bsum, int* __restrict__ boff,
    int* __restrict__ rowptr)
{
    __shared__ int sh[512];
    int t = threadIdx.x;
    int v = (t < SCAN_BLKS) ? bsum[t] : 0;
    sh[t] = v;
    __syncthreads();
    #pragma unroll
    for (int o = 1; o < 512; o <<= 1) {
        int add = (t >= o) ? sh[t - o] : 0;
        __syncthreads();
        sh[t] += add;
        __syncthreads();
    }
    if (t < SCAN_BLKS) boff[t] = sh[t] - v;
    if (t == SCAN_BLKS - 1) rowptr[NN] = sh[t];
}

__global__ __launch_bounds__(256) void scan3_kernel(
    const int* __restrict__ cnt, const int* __restrict__ boff,
    int* __restrict__ rowptr, int* __restrict__ cursor,
    float* __restrict__ dinv)
{
    __shared__ int warpincl[8];
    int idx = blockIdx.x * 256 + threadIdx.x;
    int lane = threadIdx.x & 31;
    int wid = threadIdx.x >> 5;
    int c = (idx < NN) ? cnt[idx] : 0;

    int incl = c;
    #pragma unroll
    for (int o = 1; o < 32; o <<= 1) {
        int u = __shfl_up_sync(0xFFFFFFFFu, incl, o);
        if (lane >= o) incl += u;
    }
    if (lane == 31) warpincl[wid] = incl;
    __syncthreads();
    if (threadIdx.x < 8) {
        int u = warpincl[threadIdx.x];
        #pragma unroll
        for (int o = 1; o < 8; o <<= 1) {
            int w = __shfl_up_sync(0xFFu, u, o);
            if (threadIdx.x >= o) u += w;
        }
        warpincl[threadIdx.x] = u;
    }
    __syncthreads();
    int base = boff[blockIdx.x] + (wid > 0 ? warpincl[wid - 1] : 0);
    int excl = base + incl - c;
    if (idx < NN) {
        rowptr[idx] = excl;
        cursor[idx] = excl;
        dinv[idx] = rsqrtf((float)(c + 1));
    }
}

__global__ void build_kernel(const int* __restrict__ ei,
                             int* __restrict__ cursor, int* __restrict__ col) {
    int e = blockIdx.x * blockDim.x + threadIdx.x;
    if (e < NE) {
        int s = ei[e];
        int d = ei[NE + e];
        col[atomicAdd(&cursor[d], 1)] = s;
    }
}

// ---------------------------------------------------------------------------
// Prep: fp32 -> fp16 conversions; post-join P row scaling
// ---------------------------------------------------------------------------
__global__ void tohalf_kernel(const float* __restrict__ src,
                              __half* __restrict__ dst, int n4) {
    int i = blockIdx.x * blockDim.x + threadIdx.x;
    if (i < n4) {
        float4 v = ((const float4*)src)[i];
        __half2 h0 = __floats2half2_rn(v.x, v.y);
        __half2 h1 = __floats2half2_rn(v.z, v.w);
        uint2 pack;
        pack.x = *(uint32_t*)&h0;
        pack.y = *(uint32_t*)&h1;
        ((uint2*)dst)[i] = pack;
    }
}

__global__ void pscale_kernel(__half* __restrict__ p,
                              const float* __restrict__ dinv) {
    int i = blockIdx.x * blockDim.x + threadIdx.x;
    if (i < NN * 16) {
        float dv = __ldg(&dinv[i >> 4]);
        uint4 u = ((const uint4*)p)[i];
        __half2* h = (__half2*)&u;
        #pragma unroll
        for (int k = 0; k < 4; k++) {
            float2 f = __half22float2(h[k]);
            h[k] = __floats2half2_rn(f.x * dv, f.y * dv);
        }
        ((uint4*)p)[i] = u;
    }
}

// ---------------------------------------------------------------------------
// wmma fp16 GEMM (m16n16k16, fp32 accum):  P16 = half(A @ W)
// CTA = 128 rows, A tile staged through SMEM (ldm=136 to avoid conflicts).
// COUT=128: 8 warps = 4 rg (32 rows) x 2 cg (64 cols)
// COUT=64:  8 warps = 8 rg (16 rows) x 1 cg (64 cols)
// ---------------------------------------------------------------------------
template <int COUT>
__global__ __launch_bounds__(256) void gemm_wmma_kernel(
    const __half* __restrict__ A, const __half* __restrict__ W,
    __half* __restrict__ P)
{
    constexpr int RG = (COUT == 128) ? 32 : 16;   // rows per warp tile
    constexpr int NA = RG / 16;                    // A-fragments per warp

    __shared__ __half As[128 * 136];               // padded A tile (34.8 KB)
    __shared__ float stage[8][16 * 20];            // epilogue staging (10 KB)

    const int wid = threadIdx.x >> 5;
    const int lane = threadIdx.x & 31;
    const int rowBase = blockIdx.x * 128;

    // Stage A tile: 128 rows x 128 halves, coalesced uint4 (8 halves) loads
    #pragma unroll
    for (int it = 0; it < 8; it++) {
        int idx = threadIdx.x + it * 256;          // uint4 index, 2048 total
        int r = idx >> 4;
        int c8 = (idx & 15) * 8;
        int gr = rowBase + r;
        uint4 v = (gr < NN) ? *(const uint4*)(A + (size_t)gr * 128 + c8)
                            : make_uint4(0u, 0u, 0u, 0u);
        *(uint4*)(&As[r * 136 + c8]) = v;
        idx += 2048 / 2;                            // (loop covers 2048 in 8 iters of 256)
    }
    // note: 2048 uint4 / 256 threads = 8 iterations exactly
    __syncthreads();

    const int rg = (COUT == 128) ? (wid >> 1) : wid;
    const int cg = (COUT == 128) ? (wid & 1) : 0;
    const int m0l = rg * RG;
    const int n0 = cg * 64;

    wmma::fragment<wmma::accumulator, 16, 16, 16, float> acc[NA][4];
    #pragma unroll
    for (int i = 0; i < NA; i++)
        #pragma unroll
        for (int j = 0; j < 4; j++) wmma::fill_fragment(acc[i][j], 0.0f);

    #pragma unroll
    for (int k = 0; k < 128; k += 16) {
        wmma::fragment<wmma::matrix_a, 16, 16, 16, __half, wmma::row_major> a[NA];
        #pragma unroll
        for (int i = 0; i < NA; i++)
            wmma::load_matrix_sync(a[i], &As[(m0l + i * 16) * 136 + k], 136);
        #pragma unroll
        for (int j = 0; j < 4; j++) {
            wmma::fragment<wmma::matrix_b, 16, 16, 16, __half, wmma::row_major> b;
            wmma::load_matrix_sync(b, W + (size_t)k * COUT + n0 + j * 16, COUT);
            #pragma unroll
            for (int i = 0; i < NA; i++)
                wmma::mma_sync(acc[i][j], a[i], b, acc[i][j]);
        }
    }

    const int r = lane >> 1;
    const int c0 = (lane & 1) * 8;
    #pragma unroll
    for (int i = 0; i < NA; i++) {
        #pragma unroll
        for (int j = 0; j < 4; j++) {
            wmma::store_matrix_sync(&stage[wid][0], acc[i][j], 20,
                                    wmma::mem_row_major);
            __syncwarp();
            int gr = rowBase + m0l + i * 16 + r;
            if (gr < NN) {
                const float* s = &stage[wid][r * 20 + c0];
                __half2 h0 = __floats2half2_rn(s[0], s[1]);
                __half2 h1 = __floats2half2_rn(s[2], s[3]);
                __half2 h2 = __floats2half2_rn(s[4], s[5]);
                __half2 h3 = __floats2half2_rn(s[6], s[7]);
                uint4 pack;
                pack.x = *(uint32_t*)&h0;
                pack.y = *(uint32_t*)&h1;
                pack.z = *(uint32_t*)&h2;
                pack.w = *(uint32_t*)&h3;
                *(uint4*)(P + (size_t)gr * COUT + n0 + j * 16 + c0) = pack;
            }
            __syncwarp();
        }
    }
}

// ---------------------------------------------------------------------------
// Gather + finalize: one warp per node, 8-wide unrolled (round-12 form).
// ---------------------------------------------------------------------------
__device__ __forceinline__ void add_h4(float4& acc, uint2 u) {
    __half2 a = *(__half2*)&u.x;
    __half2 b = *(__half2*)&u.y;
    float2 fa = __half22float2(a);
    float2 fb = __half22float2(b);
    acc.x += fa.x; acc.y += fa.y; acc.z += fb.x; acc.w += fb.y;
}

template <int COUT, bool RELU, bool SCALE_OUT, bool HALF_OUT>
__global__ __launch_bounds__(256) void gather_kernel(
    const __half* __restrict__ P, const int* __restrict__ rowptr,
    const int* __restrict__ col, const float* __restrict__ dinv,
    const float* __restrict__ bias, void* __restrict__ OUT)
{
    const int v = (int)((blockIdx.x * 256u + threadIdx.x) >> 5);
    const int lane = threadIdx.x & 31;
    if (v >= NN) return;

    const int start = __ldg(&rowptr[v]);
    const int end   = __ldg(&rowptr[v + 1]);
    const float dvv = __ldg(&dinv[v]);

    if (COUT == 128) {
        const size_t off = (size_t)lane * 4;
        float4 acc = make_float4(0.f, 0.f, 0.f, 0.f);
        add_h4(acc, *(const uint2*)(P + (size_t)v * 128 + off));
        int i = start;
        for (; i + 7 < end; i += 8) {
            int s[8];
            #pragma unroll
            for (int u = 0; u < 8; u++) s[u] = __ldg(&col[i + u]);
            uint2 t[8];
            #pragma unroll
            for (int u = 0; u < 8; u++)
                t[u] = *(const uint2*)(P + (size_t)s[u] * 128 + off);
            #pragma unroll
            for (int u = 0; u < 8; u++) add_h4(acc, t[u]);
        }
        for (; i + 3 < end; i += 4) {
            int s[4];
            #pragma unroll
            for (int u = 0; u < 4; u++) s[u] = __ldg(&col[i + u]);
            uint2 t[4];
            #pragma unroll
            for (int u = 0; u < 4; u++)
                t[u] = *(const uint2*)(P + (size_t)s[u] * 128 + off);
            #pragma unroll
            for (int u = 0; u < 4; u++) add_h4(acc, t[u]);
        }
        for (; i < end; i++) {
            int s0 = __ldg(&col[i]);
            add_h4(acc, *(const uint2*)(P + (size_t)s0 * 128 + off));
        }
        float4 bb = *(const float4*)(bias + off);
        float4 r = make_float4(fmaf(dvv, acc.x, bb.x), fmaf(dvv, acc.y, bb.y),
                               fmaf(dvv, acc.z, bb.z), fmaf(dvv, acc.w, bb.w));
        if (RELU) {
            r.x = fmaxf(r.x, 0.0f); r.y = fmaxf(r.y, 0.0f);
            r.z = fmaxf(r.z, 0.0f); r.w = fmaxf(r.w, 0.0f);
        }
        if (SCALE_OUT) { r.x *= dvv; r.y *= dvv; r.z *= dvv; r.w *= dvv; }
        if (HALF_OUT) {
            __half2 h0 = __floats2half2_rn(r.x, r.y);
            __half2 h1 = __floats2half2_rn(r.z, r.w);
            uint2 pack;
            pack.x = *(uint32_t*)&h0;
            pack.y = *(uint32_t*)&h1;
            *(uint2*)((__half*)OUT + (size_t)v * 128 + off) = pack;
        } else {
            *(float4*)((float*)OUT + (size_t)v * 128 + off) = r;
        }
    } else {
        const size_t off = (size_t)lane * 2;
        float2 acc = make_float2(0.f, 0.f);
        {
            float2 f = __half22float2(*(const __half2*)(P + (size_t)v * 64 + off));
            acc.x += f.x; acc.y += f.y;
        }
        int i = start;
        for (; i + 7 < end; i += 8) {
            int s[8];
            #pragma unroll
            for (int u = 0; u < 8; u++) s[u] = __ldg(&col[i + u]);
            __half2 t[8];
            #pragma unroll
            for (int u = 0; u < 8; u++)
                t[u] = *(const __half2*)(P + (size_t)s[u] * 64 + off);
            #pragma unroll
            for (int u = 0; u < 8; u++) {
                float2 f = __half22float2(t[u]);
                acc.x += f.x; acc.y += f.y;
            }
        }
        for (; i < end; i++) {
            int s0 = __ldg(&col[i]);
            float2 f = __half22float2(*(const __half2*)(P + (size_t)s0 * 64 + off));
            acc.x += f.x; acc.y += f.y;
        }
        float2 bb = *(const float2*)(bias + off);
        float2 r = make_float2(fmaf(dvv, acc.x, bb.x), fmaf(dvv, acc.y, bb.y));
        if (RELU) { r.x = fmaxf(r.x, 0.0f); r.y = fmaxf(r.y, 0.0f); }
        if (SCALE_OUT) { r.x *= dvv; r.y *= dvv; }
        if (HALF_OUT) {
            __half2 h = __floats2half2_rn(r.x, r.y);
            *(__half2*)((__half*)OUT + (size_t)v * 64 + off) = h;
        } else {
            *(float2*)((float*)OUT + (size_t)v * 64 + off) = r;
        }
    }
}

// ---------------------------------------------------------------------------
// Launch — fork/join: CSR chain on default stream, prep + GEMM1 on side stream
// ---------------------------------------------------------------------------
extern "C" void kernel_launch(void* const* d_in, const int* in_sizes, int n_in,
                              void* d_out, int out_size) {
    const float* x  = (const float*)d_in[0];
    const int*   ei = (const int*)d_in[1];
    const float* W1 = (const float*)d_in[2];
    const float* b1 = (const float*)d_in[3];
    const float* W2 = (const float*)d_in[4];
    const float* b2 = (const float*)d_in[5];
    const float* W3 = (const float*)d_in[6];
    const float* b3 = (const float*)d_in[7];
    float* out = (float*)d_out;

    float *dinv;
    __half *x16, *p16, *h16, *w1h, *w2h, *w3h;
    int *cnt, *bsum, *boff, *rowptr, *cursor, *col;
    cudaGetSymbolAddress((void**)&dinv,   g_dinv);
    cudaGetSymbolAddress((void**)&x16,    g_x16);
    cudaGetSymbolAddress((void**)&p16,    g_p16);
    cudaGetSymbolAddress((void**)&h16,    g_h16);
    cudaGetSymbolAddress((void**)&w1h,    g_w1h);
    cudaGetSymbolAddress((void**)&w2h,    g_w2h);
    cudaGetSymbolAddress((void**)&w3h,    g_w3h);
    cudaGetSymbolAddress((void**)&cnt,    g_cnt);
    cudaGetSymbolAddress((void**)&bsum,   g_bsum);
    cudaGetSymbolAddress((void**)&boff,   g_boff);
    cudaGetSymbolAddress((void**)&rowptr, g_rowptr);
    cudaGetSymbolAddress((void**)&cursor, g_cursor);
    cudaGetSymbolAddress((void**)&col,    g_col);

    const int TB = 256;
    const int nBlkN     = (NN + TB - 1) / TB;
    const int nBlkE     = (NE + TB - 1) / TB;
    const int gemmBlk   = (NN + 127) / 128;          // 782, both GEMMs
    const int gatherBlk = (NN * 32 + TB - 1) / TB;

    cudaStream_t s2;
    cudaEvent_t eFork, eJoin;
    cudaStreamCreateWithFlags(&s2, cudaStreamNonBlocking);
    cudaEventCreateWithFlags(&eFork, cudaEventDisableTiming);
    cudaEventCreateWithFlags(&eJoin, cudaEventDisableTiming);

    cudaEventRecord(eFork, 0);
    cudaStreamWaitEvent(s2, eFork, 0);

    // side stream: fp16 prep + raw layer-1 GEMM (independent of edge_index)
    tohalf_kernel<<<(128 * 128 / 4 + TB - 1) / TB, TB, 0, s2>>>(W1, w1h, 128 * 128 / 4);
    tohalf_kernel<<<(128 * 128 / 4 + TB - 1) / TB, TB, 0, s2>>>(W2, w2h, 128 * 128 / 4);
    tohalf_kernel<<<(128 * 64 / 4 + TB - 1) / TB, TB, 0, s2>>>(W3, w3h, 128 * 64 / 4);
    tohalf_kernel<<<(NN * 32 + TB - 1) / TB, TB, 0, s2>>>(x, x16, NN * 32);
    gemm_wmma_kernel<128><<<gemmBlk, TB, 0, s2>>>(x16, w1h, p16);
    cudaEventRecord(eJoin, s2);

    // default stream: CSR build + normalization
    zero_cnt_kernel<<<nBlkN, TB>>>(cnt);
    hist_kernel<<<nBlkE, TB>>>(ei, cnt);
    scan1_kernel<<<SCAN_BLKS, TB>>>(cnt, bsum);
    scan2_kernel<<<1, 512>>>(bsum, boff, rowptr);
    scan3_kernel<<<SCAN_BLKS, TB>>>(cnt, boff, rowptr, cursor, dinv);
    build_kernel<<<nBlkE, TB>>>(ei, cursor, col);

    // join
    cudaStreamWaitEvent(0, eJoin, 0);

    // layer 1: scale P by dinv[row], then gather (emit fp16 h)
    pscale_kernel<<<(NN * 16 + TB - 1) / TB, TB>>>(p16, dinv);
    gather_kernel<128, true, true, true><<<gatherBlk, TB>>>(
        p16, rowptr, col, dinv, b1, h16);
    // layer 2
    gemm_wmma_kernel<128><<<gemmBlk, TB>>>(h16, w2h, p16);
    gather_kernel<128, true, true, true><<<gatherBlk, TB>>>(
        p16, rowptr, col, dinv, b2, h16);
    // layer 3
    gemm_wmma_kernel<64><<<gemmBlk, TB>>>(h16, w3h, p16);
    gather_kernel<64, false, false, false><<<gatherBlk, TB>>>(
        p16, rowptr, col, dinv, b3, out);
}